// round 5
// baseline (speedup 1.0000x reference)
#include <cuda_runtime.h>
#include <math.h>

#define BSZ  512
#define TLEN 64
#define XDIM 512
#define EDIM 1024
#define UDIM 1024
#define NBX_ATT 8   // gridDim.x of the attention GEMM (1024/128)

// ---------------- static scratch (no allocations allowed) ----------------
__device__ float g_tanhE[(size_t)BSZ * TLEN * EDIM];          // 134 MB
__device__ float g_hWa  [(size_t)BSZ * UDIM];                 // tanh(h) @ Wa[:U]
__device__ float g_epart[(size_t)BSZ * TLEN * NBX_ATT];       // per-N-block partial e
__device__ float g_ct   [(size_t)BSZ * EDIM];                 // context vectors
__device__ float g_G1   [(size_t)BSZ * 3 * UDIM];             // x@kernel + bias
__device__ float g_G2   [(size_t)BSZ * 2 * UDIM];             // h@rker[:, :2048] (z,r parts)
__device__ float g_z    [(size_t)BSZ * UDIM];                 // z gate
__device__ float g_rh   [(size_t)BSZ * UDIM];                 // r * h
__device__ float g_Ghh  [(size_t)BSZ * UDIM];                 // (r*h) @ rker[:, 2048:]

// ---------------- tanh(E) precompute ----------------
__global__ void tanh4_kernel(const float4* __restrict__ in, float4* __restrict__ out, int n4)
{
    int i = blockIdx.x * blockDim.x + threadIdx.x;
    if (i < n4) {
        float4 v = in[i];
        v.x = tanhf(v.x); v.y = tanhf(v.y); v.z = tanhf(v.z); v.w = tanhf(v.w);
        out[i] = v;
    }
}

// ---------------- generic 128x128x8 fp32 SGEMM, 8x8 per thread ----------------
enum { AM_PLAIN = 0, AM_TANH = 1, AM_CONCAT = 2 };
enum { EP_STORE = 0, EP_BIAS = 1, EP_ATT = 2 };

template<int AMODE, int EMODE, int KDIM>
__global__ __launch_bounds__(256)
void sgemm_kernel(const float* __restrict__ A0, const float* __restrict__ A1,
                  const float* __restrict__ Bm, int koff, int ldb,
                  float* __restrict__ C, int ldc,
                  const float* __restrict__ hWa, const float* __restrict__ Va,
                  const float* __restrict__ bias)
{
    __shared__ float As[8][128];
    __shared__ float Bs[8][128];
    const int tid  = threadIdx.x;
    const int tx   = tid & 15;
    const int ty   = tid >> 4;
    const int row0 = blockIdx.y * 128;
    const int col0 = blockIdx.x * 128;
    const int ar   = tid >> 1;          // A tile: 128 rows x 8 k, 2 threads/row
    const int ac   = (tid & 1) * 4;
    const int br   = tid >> 5;          // B tile: 8 k x 128 cols
    const int bc   = (tid & 31) * 4;

    float acc[8][8];
    #pragma unroll
    for (int i = 0; i < 8; ++i)
        #pragma unroll
        for (int j = 0; j < 8; ++j)
            acc[i][j] = 0.f;

    for (int kt = 0; kt < KDIM; kt += 8) {
        float4 av;
        const int k4 = kt + ac;
        if (AMODE == AM_CONCAT) {
            // x = [inputs (512) | c_t (1024)]; 512 % 4 == 0 so a float4 never straddles
            if (k4 < XDIM)
                av = *reinterpret_cast<const float4*>(&A0[(size_t)(row0 + ar) * XDIM + k4]);
            else
                av = *reinterpret_cast<const float4*>(&A1[(size_t)(row0 + ar) * EDIM + (k4 - XDIM)]);
        } else {
            av = *reinterpret_cast<const float4*>(&A0[(size_t)(row0 + ar) * KDIM + k4]);
            if (AMODE == AM_TANH) {
                av.x = tanhf(av.x); av.y = tanhf(av.y); av.z = tanhf(av.z); av.w = tanhf(av.w);
            }
        }
        As[ac + 0][ar] = av.x;
        As[ac + 1][ar] = av.y;
        As[ac + 2][ar] = av.z;
        As[ac + 3][ar] = av.w;

        float4 bv = *reinterpret_cast<const float4*>(
            &Bm[(size_t)(koff + kt + br) * ldb + col0 + bc]);
        Bs[br][bc + 0] = bv.x;
        Bs[br][bc + 1] = bv.y;
        Bs[br][bc + 2] = bv.z;
        Bs[br][bc + 3] = bv.w;
        __syncthreads();

        #pragma unroll
        for (int kk = 0; kk < 8; ++kk) {
            float ra[8], rb[8];
            #pragma unroll
            for (int i = 0; i < 8; ++i) ra[i] = As[kk][ty * 8 + i];
            #pragma unroll
            for (int j = 0; j < 8; ++j) rb[j] = Bs[kk][tx * 8 + j];
            #pragma unroll
            for (int i = 0; i < 8; ++i)
                #pragma unroll
                for (int j = 0; j < 8; ++j)
                    acc[i][j] = fmaf(ra[i], rb[j], acc[i][j]);
        }
        __syncthreads();
    }

    if (EMODE == EP_ATT) {
        // e-partials: sum_j tanh(EWa + hWa[b,j]) * Va[j] over this block's 128 cols.
        // Thread rows ty*8..ty*8+7 all lie in one 64-row (one b) group.
        const int b = (row0 + ty * 8) >> 6;   // m / TLEN
        float va[8], hv[8];
        #pragma unroll
        for (int j = 0; j < 8; ++j) {
            const int jj = col0 + tx * 8 + j;
            va[j] = Va[jj];
            hv[j] = hWa[(size_t)b * UDIM + jj];
        }
        #pragma unroll
        for (int i = 0; i < 8; ++i) {
            const int m = row0 + ty * 8 + i;
            float s = 0.f;
            #pragma unroll
            for (int j = 0; j < 8; ++j)
                s += tanhf(acc[i][j] + hv[j]) * va[j];
            #pragma unroll
            for (int off = 8; off > 0; off >>= 1)
                s += __shfl_down_sync(0xffffffffu, s, off, 16);
            if (tx == 0)
                C[(size_t)m * NBX_ATT + blockIdx.x] = s;   // deterministic, no atomics
        }
    } else {
        #pragma unroll
        for (int i = 0; i < 8; ++i) {
            const int m = row0 + ty * 8 + i;
            #pragma unroll
            for (int j = 0; j < 8; j += 4) {
                const int jj = col0 + tx * 8 + j;
                float4 o;
                o.x = acc[i][j + 0];
                o.y = acc[i][j + 1];
                o.z = acc[i][j + 2];
                o.w = acc[i][j + 3];
                if (EMODE == EP_BIAS) {
                    o.x += bias[jj + 0]; o.y += bias[jj + 1];
                    o.z += bias[jj + 2]; o.w += bias[jj + 3];
                }
                *reinterpret_cast<float4*>(&C[(size_t)m * ldc + jj]) = o;
            }
        }
    }
}

// ---------------- softmax over T + context vector; writes alpha to out ----------------
__global__ __launch_bounds__(256)
void attn_kernel(const float* __restrict__ E, float* __restrict__ out)
{
    const int b   = blockIdx.x;
    const int tid = threadIdx.x;
    __shared__ float alpha[TLEN];

    if (tid < TLEN) {
        const float* ep = g_epart + (size_t)(b * TLEN + tid) * NBX_ATT;
        float e = 0.f;
        #pragma unroll
        for (int p = 0; p < NBX_ATT; ++p) e += ep[p];
        alpha[tid] = e;
    }
    __syncthreads();
    if (tid < 32) {
        float v0 = alpha[tid], v1 = alpha[tid + 32];
        float mx = fmaxf(v0, v1);
        #pragma unroll
        for (int off = 16; off > 0; off >>= 1)
            mx = fmaxf(mx, __shfl_xor_sync(0xffffffffu, mx, off));
        float e0 = expf(v0 - mx), e1 = expf(v1 - mx);
        float s = e0 + e1;
        #pragma unroll
        for (int off = 16; off > 0; off >>= 1)
            s += __shfl_xor_sync(0xffffffffu, s, off);
        float inv = 1.f / s;
        alpha[tid]      = e0 * inv;
        alpha[tid + 32] = e1 * inv;
    }
    __syncthreads();
    if (tid < TLEN)
        out[(size_t)b * 1088 + tid] = alpha[tid];

    // c_t[b,:] = sum_t alpha[t] * E[b,t,:]   (coalesced: 256 threads x 4 elems)
    const float* Eb = E + (size_t)b * TLEN * EDIM;
    float a0 = 0.f, a1 = 0.f, a2 = 0.f, a3 = 0.f;
    for (int t = 0; t < TLEN; ++t) {
        const float w = alpha[t];
        const float* row = Eb + (size_t)t * EDIM;
        a0 = fmaf(w, row[tid +   0], a0);
        a1 = fmaf(w, row[tid + 256], a1);
        a2 = fmaf(w, row[tid + 512], a2);
        a3 = fmaf(w, row[tid + 768], a3);
    }
    float* ct = g_ct + (size_t)b * EDIM;
    ct[tid +   0] = a0;
    ct[tid + 256] = a1;
    ct[tid + 512] = a2;
    ct[tid + 768] = a3;
}

// ---------------- gate kernel: z, r from G1/G2; store z and r*h ----------------
__global__ __launch_bounds__(256)
void gates_kernel(const float* __restrict__ h)
{
    const int idx = blockIdx.x * blockDim.x + threadIdx.x;
    if (idx >= BSZ * UDIM) return;
    const int m = idx >> 10;
    const int j = idx & 1023;
    const float* G1 = g_G1 + (size_t)m * 3 * UDIM;
    const float* G2 = g_G2 + (size_t)m * 2 * UDIM;
    float z = fminf(fmaxf(0.2f * (G1[j]        + G2[j])        + 0.5f, 0.f), 1.f);
    float r = fminf(fmaxf(0.2f * (G1[j + 1024] + G2[j + 1024]) + 0.5f, 0.f), 1.f);
    g_z[idx]  = z;
    g_rh[idx] = r * h[idx];   // NOTE: (r*h) feeds the hh GEMM — Python parses r*h@rh as (r*h)@rh
}

// ---------------- final: hh = tanh(G1_hh + (r*h)@rh); h_new -> out ----------------
__global__ __launch_bounds__(256)
void gru_final_kernel(const float* __restrict__ h, float* __restrict__ out)
{
    const int idx = blockIdx.x * blockDim.x + threadIdx.x;
    if (idx >= BSZ * UDIM) return;
    const int m = idx >> 10;
    const int j = idx & 1023;
    float hh = tanhf(g_G1[(size_t)m * 3 * UDIM + 2048 + j] + g_Ghh[idx]);
    float z  = g_z[idx];
    float hv = h[idx];
    out[(size_t)m * 1088 + 64 + j] = z * hv + (1.f - z) * hh;
}

// ---------------- launch ----------------
extern "C" void kernel_launch(void* const* d_in, const int* in_sizes, int n_in,
                              void* d_out, int out_size)
{
    (void)in_sizes; (void)n_in; (void)out_size;
    const float* inputs = (const float*)d_in[0];   // (512, 512)
    const float* h      = (const float*)d_in[1];   // (512, 1024)
    const float* E      = (const float*)d_in[2];   // (512, 64, 1024)
    const float* kern   = (const float*)d_in[3];   // (1536, 3072)
    const float* rker   = (const float*)d_in[4];   // (1024, 3072)
    const float* bias   = (const float*)d_in[5];   // (3072,)
    const float* Wa     = (const float*)d_in[6];   // (2048, 1024)
    const float* Va     = (const float*)d_in[7];   // (1024, 1)
    float* out = (float*)d_out;                    // (512, 1088)

    float *tanhE, *hWa, *epart, *ct, *G1, *G2, *rh, *Ghh;
    cudaGetSymbolAddress((void**)&tanhE, g_tanhE);
    cudaGetSymbolAddress((void**)&hWa,   g_hWa);
    cudaGetSymbolAddress((void**)&epart, g_epart);
    cudaGetSymbolAddress((void**)&ct,    g_ct);
    cudaGetSymbolAddress((void**)&G1,    g_G1);
    cudaGetSymbolAddress((void**)&G2,    g_G2);
    cudaGetSymbolAddress((void**)&rh,    g_rh);
    cudaGetSymbolAddress((void**)&Ghh,   g_Ghh);

    // 1. tanh(E) precompute
    const int n4 = BSZ * TLEN * EDIM / 4;
    tanh4_kernel<<<n4 / 256, 256>>>((const float4*)E, (float4*)tanhE, n4);

    // 2. hWa = tanh(h) @ Wa[:U]          M=512 N=1024 K=1024
    sgemm_kernel<AM_TANH, EP_STORE, UDIM><<<dim3(8, 4), 256>>>(
        h, nullptr, Wa, 0, UDIM, hWa, UDIM, nullptr, nullptr, nullptr);

    // 3. big attention GEMM + fused e-partials   M=32768 N=1024 K=1024
    sgemm_kernel<AM_PLAIN, EP_ATT, EDIM><<<dim3(NBX_ATT, 256), 256>>>(
        tanhE, nullptr, Wa, UDIM, UDIM, epart, 0, hWa, Va, nullptr);

    // 4. softmax + alpha-out + context
    attn_kernel<<<BSZ, 256>>>(E, out);

    // 5. G1 = [inputs|c_t] @ kernel + bias       M=512 N=3072 K=1536
    sgemm_kernel<AM_CONCAT, EP_BIAS, XDIM + EDIM><<<dim3(24, 4), 256>>>(
        inputs, ct, kern, 0, 3 * UDIM, G1, 3 * UDIM, nullptr, nullptr, bias);

    // 6. G2 = h @ rker[:, :2048]  (z and r parts only)   M=512 N=2048 K=1024
    sgemm_kernel<AM_PLAIN, EP_STORE, UDIM><<<dim3(16, 4), 256>>>(
        h, nullptr, rker, 0, 3 * UDIM, G2, 2 * UDIM, nullptr, nullptr, nullptr);

    // 7. z, r gates; rh = r * h
    gates_kernel<<<(BSZ * UDIM + 255) / 256, 256>>>(h);

    // 8. Ghh = (r*h) @ rker[:, 2048:]            M=512 N=1024 K=1024
    sgemm_kernel<AM_PLAIN, EP_STORE, UDIM><<<dim3(8, 4), 256>>>(
        rh, nullptr, rker + 2048, 0, 3 * UDIM, Ghh, UDIM, nullptr, nullptr, nullptr);

    // 9. h_new -> out
    gru_final_kernel<<<(BSZ * UDIM + 255) / 256, 256>>>(h, out);
}

// round 7
// speedup vs baseline: 1.8027x; 1.8027x over previous
#include <cuda_runtime.h>
#include <math.h>
#include <stdint.h>

#define BSZ  512
#define TLEN 64
#define XDIM 512
#define EDIM 1024
#define UDIM 1024
#define NBX_ATT 4          // N blocks of 256 in the attention GEMM (1024/256)

#define TM 128
#define TN 256
#define TK 32

#if defined(__CUDA_ARCH_FEAT_SM103_ALL) || defined(__CUDA_ARCH_FEAT_SM100_ALL) || defined(__CUDA_ARCH_FEAT_SM101_ALL)
#define HAS_TCGEN05 1
#else
#define HAS_TCGEN05 0
#endif

// ---------------- static scratch ----------------
__device__ float g_tanhE[(size_t)BSZ * TLEN * EDIM];          // 134 MB
__device__ float g_hWa  [(size_t)BSZ * UDIM];
__device__ float g_epart[(size_t)BSZ * TLEN * NBX_ATT];
__device__ float g_ct   [(size_t)BSZ * EDIM];
__device__ float g_G1   [(size_t)BSZ * 3 * UDIM];
__device__ float g_G2   [(size_t)BSZ * 2 * UDIM];
__device__ float g_z    [(size_t)BSZ * UDIM];
__device__ float g_rh   [(size_t)BSZ * UDIM];
__device__ float g_Ghh  [(size_t)BSZ * UDIM];
// K-major transposed weights: W_T[n][k]
__device__ float g_WaT_lo[(size_t)UDIM * UDIM];               // Wa[:1024]^T
__device__ float g_WaT_hi[(size_t)UDIM * UDIM];               // Wa[1024:]^T
__device__ float g_kernT [(size_t)3 * UDIM * (XDIM + EDIM)];  // kern^T  [3072][1536]
__device__ float g_rkerT [(size_t)3 * UDIM * UDIM];           // rker^T  [3072][1024]

// ---------------- PTX helpers (only referenced from the sm_103a branch) ----------------
#if HAS_TCGEN05
__device__ __forceinline__ uint32_t smem_u32(const void* p) {
    uint32_t a;
    asm("{ .reg .u64 t; cvta.to.shared.u64 t, %1; cvt.u32.u64 %0, t; }" : "=r"(a) : "l"(p));
    return a;
}
__device__ __forceinline__ uint32_t f2tf32(float f) {
    uint32_t r;
    asm("cvt.rna.tf32.f32 %0, %1;" : "=r"(r) : "f"(f));
    return r;
}
#define SW128(x) ((x) ^ (((x) >> 3) & 0x70))

#define TCG_ALLOC(sm, n)  asm volatile("tcgen05.alloc.cta_group::1.sync.aligned.shared::cta.b32 [%0], %1;" :: "r"(sm), "r"(n) : "memory")
#define TCG_DEALLOC(t, n) asm volatile("tcgen05.dealloc.cta_group::1.sync.aligned.b32 %0, %1;" :: "r"(t), "r"(n))
#define TCG_RELINQ()      asm volatile("tcgen05.relinquish_alloc_permit.cta_group::1.sync.aligned;")
#define TCG_COMMIT(mb)    asm volatile("tcgen05.commit.cta_group::1.mbarrier::arrive::one.shared::cluster.b64 [%0];" :: "r"(mb) : "memory")
#define TCG_FENCE_AFTER() asm volatile("tcgen05.fence::after_thread_sync;" ::: "memory")
#define TCG_FENCE_BEFORE() asm volatile("tcgen05.fence::before_thread_sync;" ::: "memory")
#define TCG_WAIT_LD()     asm volatile("tcgen05.wait::ld.sync.aligned;" ::: "memory")
#define FENCE_ASYNC()     asm volatile("fence.proxy.async.shared::cta;" ::: "memory")
#define MBAR_INIT(mb, c)  asm volatile("mbarrier.init.shared.b64 [%0], %1;" :: "r"(mb), "r"(c) : "memory")

__device__ __forceinline__ void mbar_wait(uint32_t mb, uint32_t parity) {
    uint32_t done;
    asm volatile("{\n\t.reg .pred p;\n\t"
        "mbarrier.try_wait.parity.acquire.cta.shared::cta.b64 p, [%1], %2;\n\t"
        "selp.b32 %0, 1, 0, p;\n\t}"
        : "=r"(done) : "r"(mb), "r"(parity) : "memory");
    if (!done) {
        asm volatile("{\n\t.reg .pred P1;\n\t"
            "W_%=:\n\t"
            "mbarrier.try_wait.parity.acquire.cta.shared::cta.b64 P1, [%0], %1, 0x989680;\n\t"
            "@P1 bra.uni D_%=;\n\t"
            "bra.uni W_%=;\n\t"
            "D_%=:\n\t}"
            :: "r"(mb), "r"(parity) : "memory");
    }
}
__device__ __forceinline__ void mma_tf32_ss(uint32_t d, uint64_t ad, uint64_t bd,
                                            uint32_t idesc, uint32_t acc) {
    asm volatile("{\n\t.reg .pred p;\n\t"
        "setp.ne.u32 p, %5, 0;\n\t"
        "tcgen05.mma.cta_group::1.kind::tf32 [%0], %1, %2, %3, {%4, %4, %4, %4}, p;\n\t}"
        :: "r"(d), "l"(ad), "l"(bd), "r"(idesc), "r"(0u), "r"(acc) : "memory");
}
__device__ __forceinline__ void tmem_ld32(uint32_t* r, uint32_t a) {
    asm volatile("tcgen05.ld.sync.aligned.32x32b.x32.b32 "
        "{%0,%1,%2,%3,%4,%5,%6,%7,%8,%9,%10,%11,%12,%13,%14,%15,"
        "%16,%17,%18,%19,%20,%21,%22,%23,%24,%25,%26,%27,%28,%29,%30,%31}, [%32];"
        : "=r"(r[0]),"=r"(r[1]),"=r"(r[2]),"=r"(r[3]),"=r"(r[4]),"=r"(r[5]),"=r"(r[6]),"=r"(r[7]),
          "=r"(r[8]),"=r"(r[9]),"=r"(r[10]),"=r"(r[11]),"=r"(r[12]),"=r"(r[13]),"=r"(r[14]),"=r"(r[15]),
          "=r"(r[16]),"=r"(r[17]),"=r"(r[18]),"=r"(r[19]),"=r"(r[20]),"=r"(r[21]),"=r"(r[22]),"=r"(r[23]),
          "=r"(r[24]),"=r"(r[25]),"=r"(r[26]),"=r"(r[27]),"=r"(r[28]),"=r"(r[29]),"=r"(r[30]),"=r"(r[31])
        : "r"(a));
}
// SW128 K-major smem descriptor (LBO=1, SBO=64, version=1)
__device__ __forceinline__ uint64_t mk_desc(uint32_t addr) {
    const uint64_t base = (uint64_t(2) << 61) | (uint64_t(1) << 46)
                        | (uint64_t(64) << 32) | (uint64_t(1) << 16);
    return base | ((uint64_t)(addr >> 4) & 0x3FFF);
}
#endif // HAS_TCGEN05

// ---------------- misc elementwise / transpose ----------------
__global__ void tanh4_kernel(const float4* __restrict__ in, float4* __restrict__ out, int n4)
{
    int i = blockIdx.x * blockDim.x + threadIdx.x;
    if (i < n4) {
        float4 v = in[i];
        v.x = tanhf(v.x); v.y = tanhf(v.y); v.z = tanhf(v.z); v.w = tanhf(v.w);
        out[i] = v;
    }
}

// dst[n*K + k] = src[k*ld + n]
__global__ __launch_bounds__(256)
void transpose_kernel(const float* __restrict__ src, int ld, int K, float* __restrict__ dst)
{
    __shared__ float t[32][33];
    const int tx = threadIdx.x, ty = threadIdx.y;
    const int n0 = blockIdx.x * 32, k0 = blockIdx.y * 32;
    #pragma unroll
    for (int i = 0; i < 32; i += 8)
        t[ty + i][tx] = src[(size_t)(k0 + ty + i) * ld + n0 + tx];
    __syncthreads();
    #pragma unroll
    for (int i = 0; i < 32; i += 8)
        dst[(size_t)(n0 + ty + i) * K + k0 + tx] = t[tx][ty + i];
}

// ---------------- GEMM: 128x256 tile ----------------
enum { AM_PLAIN = 0, AM_TANH = 1, AM_CONCAT = 2 };
enum { EP_STORE = 0, EP_BIAS = 1, EP_ATT = 2 };

#define SM_A0   0
#define SM_A1   16384
#define SM_B0   32768
#define SM_B1   65536
#define SM_CTRL 98304         // [tmem_ptr:4][pad:4][mbar0:8][mbar1:8]
#define SM_TOTAL (98304 + 128)

template<int AMODE, int EMODE>
__global__ __launch_bounds__(128)
void tgemm_kernel(const float* __restrict__ A0, const float* __restrict__ A1, int lda,
                  const float* __restrict__ Bt, int ldb, int nK,
                  float* __restrict__ C, int ldc,
                  const float* __restrict__ hWa, const float* __restrict__ Va,
                  const float* __restrict__ bias)
{
    extern __shared__ char smc[];
    const int tid = threadIdx.x;
    const int row0 = blockIdx.y * TM;
    const int col0 = blockIdx.x * TN;

#if HAS_TCGEN05
    // ================= tcgen05 tf32 path (sm_103a cubin) =================
    const uint32_t sb  = smem_u32(smc);
    const int wid = tid >> 5;
    const int lid = tid & 31;

    if (wid == 0) { TCG_ALLOC(sb + SM_CTRL, TN); TCG_RELINQ(); }
    if (tid == 0) { MBAR_INIT(sb + SM_CTRL + 8, 1); MBAR_INIT(sb + SM_CTRL + 16, 1); }
    __syncthreads();
    uint32_t tmem;
    asm volatile("ld.shared.b32 %0, [%1];" : "=r"(tmem) : "r"(sb + SM_CTRL));

    const uint32_t idesc = (1u << 4) | (2u << 7) | (2u << 10)
                         | ((TN / 8) << 17) | ((TM / 16) << 24);

    int ph0 = 0, ph1 = 0;
    for (int kt = 0; kt < nK; ++kt) {
        const int buf = kt & 1;
        if (kt >= 2) {
            if (buf == 0) { mbar_wait(sb + SM_CTRL + 8,  ph0); ph0 ^= 1; }
            else          { mbar_wait(sb + SM_CTRL + 16, ph1); ph1 ^= 1; }
        }
        const int k0 = kt * TK;
        // A tile: 128 rows x 32 fp32
        char* abase = smc + (buf ? SM_A1 : SM_A0);
        #pragma unroll
        for (int i = 0; i < 8; ++i) {
            const int slot = i * 128 + tid;
            const int r = slot >> 3, q = slot & 7;
            float4 v;
            if (AMODE == AM_CONCAT) {
                if (k0 < XDIM)
                    v = *reinterpret_cast<const float4*>(&A0[(size_t)(row0 + r) * XDIM + k0 + q * 4]);
                else
                    v = *reinterpret_cast<const float4*>(&A1[(size_t)(row0 + r) * EDIM + (k0 - XDIM) + q * 4]);
            } else {
                v = *reinterpret_cast<const float4*>(&A0[(size_t)(row0 + r) * lda + k0 + q * 4]);
                if (AMODE == AM_TANH) {
                    v.x = tanhf(v.x); v.y = tanhf(v.y); v.z = tanhf(v.z); v.w = tanhf(v.w);
                }
            }
            uint4 u = make_uint4(f2tf32(v.x), f2tf32(v.y), f2tf32(v.z), f2tf32(v.w));
            *reinterpret_cast<uint4*>(abase + SW128(r * 128 + q * 16)) = u;
        }
        // B tile: 256 n-rows x 32 fp32 (K-major)
        char* bbase = smc + (buf ? SM_B1 : SM_B0);
        #pragma unroll
        for (int i = 0; i < 16; ++i) {
            const int slot = i * 128 + tid;
            const int r = slot >> 3, q = slot & 7;
            float4 v = *reinterpret_cast<const float4*>(&Bt[(size_t)(col0 + r) * ldb + k0 + q * 4]);
            uint4 u = make_uint4(f2tf32(v.x), f2tf32(v.y), f2tf32(v.z), f2tf32(v.w));
            *reinterpret_cast<uint4*>(bbase + SW128(r * 128 + q * 16)) = u;
        }
        __syncthreads();
        if (tid == 0) {
            FENCE_ASYNC();
            const uint64_t ad = mk_desc(sb + (buf ? SM_A1 : SM_A0));
            const uint64_t bd = mk_desc(sb + (buf ? SM_B1 : SM_B0));
            #pragma unroll
            for (int s = 0; s < 4; ++s)
                mma_tf32_ss(tmem, ad + s * 2, bd + s * 2, idesc, (kt > 0 || s > 0) ? 1u : 0u);
            TCG_COMMIT(sb + SM_CTRL + 8 + buf * 8);
        }
    }
    {
        const int lb = (nK - 1) & 1;
        mbar_wait(sb + SM_CTRL + 8 + lb * 8, lb == 0 ? ph0 : ph1);
    }
    TCG_FENCE_AFTER();

    // epilogue
    const int m = row0 + wid * 32 + lid;
    if (EMODE == EP_ATT) {
        const int b = m >> 6;
        const float* hrow = hWa + (size_t)b * UDIM;
        float s = 0.f;
        #pragma unroll
        for (int c = 0; c < 8; ++c) {
            uint32_t regs[32];
            tmem_ld32(regs, tmem + c * 32);
            TCG_WAIT_LD();
            const int jj0 = col0 + c * 32;
            #pragma unroll
            for (int j = 0; j < 32; ++j)
                s += tanhf(__uint_as_float(regs[j]) + hrow[jj0 + j]) * Va[jj0 + j];
        }
        C[(size_t)m * NBX_ATT + blockIdx.x] = s;
    } else {
        #pragma unroll
        for (int c = 0; c < 8; ++c) {
            uint32_t regs[32];
            tmem_ld32(regs, tmem + c * 32);
            TCG_WAIT_LD();
            const int jj0 = col0 + c * 32;
            #pragma unroll
            for (int j = 0; j < 32; j += 4) {
                float4 o;
                o.x = __uint_as_float(regs[j + 0]);
                o.y = __uint_as_float(regs[j + 1]);
                o.z = __uint_as_float(regs[j + 2]);
                o.w = __uint_as_float(regs[j + 3]);
                if (EMODE == EP_BIAS) {
                    o.x += bias[jj0 + j + 0]; o.y += bias[jj0 + j + 1];
                    o.z += bias[jj0 + j + 2]; o.w += bias[jj0 + j + 3];
                }
                *reinterpret_cast<float4*>(&C[(size_t)m * ldc + jj0 + j]) = o;
            }
        }
    }
    TCG_FENCE_BEFORE();
    __syncthreads();
    if (wid == 0) TCG_DEALLOC(tmem, TN);

#else
    // ============ FFMA fallback (compiles on plain sm_103; same semantics) ============
    float* Bs = reinterpret_cast<float*>(smc);       // 32 x 64 tile of B
    const int Ktot = nK * TK;
    const int m = row0 + tid;                        // one M-row per thread
    float s_att = 0.f;

    for (int nc = 0; nc < 4; ++nc) {                 // 4 x 64-col chunks of TN=256
        float acc[64];
        #pragma unroll
        for (int j = 0; j < 64; ++j) acc[j] = 0.f;

        for (int kt = 0; kt < Ktot; kt += 32) {
            for (int i = tid; i < 32 * 64; i += 128) {
                const int kk = i & 31, j = i >> 5;
                Bs[kk * 64 + j] = Bt[(size_t)(col0 + nc * 64 + j) * ldb + kt + kk];
            }
            __syncthreads();

            float av[32];
            #pragma unroll
            for (int q = 0; q < 32; q += 4) {
                const int k4 = kt + q;
                float4 v;
                if (AMODE == AM_CONCAT) {
                    if (k4 < XDIM)
                        v = *reinterpret_cast<const float4*>(&A0[(size_t)m * XDIM + k4]);
                    else
                        v = *reinterpret_cast<const float4*>(&A1[(size_t)m * EDIM + (k4 - XDIM)]);
                } else {
                    v = *reinterpret_cast<const float4*>(&A0[(size_t)m * lda + k4]);
                    if (AMODE == AM_TANH) {
                        v.x = tanhf(v.x); v.y = tanhf(v.y); v.z = tanhf(v.z); v.w = tanhf(v.w);
                    }
                }
                av[q] = v.x; av[q + 1] = v.y; av[q + 2] = v.z; av[q + 3] = v.w;
            }
            #pragma unroll 4
            for (int kk = 0; kk < 32; ++kk) {
                const float a = av[kk];
                #pragma unroll
                for (int j = 0; j < 64; ++j)
                    acc[j] = fmaf(a, Bs[kk * 64 + j], acc[j]);
            }
            __syncthreads();
        }

        const int jj0 = col0 + nc * 64;
        if (EMODE == EP_ATT) {
            const int b = m >> 6;
            for (int j = 0; j < 64; ++j)
                s_att += tanhf(acc[j] + hWa[(size_t)b * UDIM + jj0 + j]) * Va[jj0 + j];
        } else {
            for (int j = 0; j < 64; ++j) {
                float o = acc[j];
                if (EMODE == EP_BIAS) o += bias[jj0 + j];
                C[(size_t)m * ldc + jj0 + j] = o;
            }
        }
    }
    if (EMODE == EP_ATT)
        C[(size_t)m * NBX_ATT + blockIdx.x] = s_att;
#endif
}

// ---------------- softmax over T + context; writes alpha to out ----------------
__global__ __launch_bounds__(256)
void attn_kernel(const float* __restrict__ E, float* __restrict__ out)
{
    const int b   = blockIdx.x;
    const int tid = threadIdx.x;
    __shared__ float alpha[TLEN];

    if (tid < TLEN) {
        const float* ep = g_epart + (size_t)(b * TLEN + tid) * NBX_ATT;
        float e = 0.f;
        #pragma unroll
        for (int p = 0; p < NBX_ATT; ++p) e += ep[p];
        alpha[tid] = e;
    }
    __syncthreads();
    if (tid < 32) {
        float v0 = alpha[tid], v1 = alpha[tid + 32];
        float mx = fmaxf(v0, v1);
        #pragma unroll
        for (int off = 16; off > 0; off >>= 1)
            mx = fmaxf(mx, __shfl_xor_sync(0xffffffffu, mx, off));
        float e0 = expf(v0 - mx), e1 = expf(v1 - mx);
        float s = e0 + e1;
        #pragma unroll
        for (int off = 16; off > 0; off >>= 1)
            s += __shfl_xor_sync(0xffffffffu, s, off);
        float inv = 1.f / s;
        alpha[tid]      = e0 * inv;
        alpha[tid + 32] = e1 * inv;
    }
    __syncthreads();
    if (tid < TLEN)
        out[(size_t)b * 1088 + tid] = alpha[tid];

    const float* Eb = E + (size_t)b * TLEN * EDIM;
    float a0 = 0.f, a1 = 0.f, a2 = 0.f, a3 = 0.f;
    for (int t = 0; t < TLEN; ++t) {
        const float w = alpha[t];
        const float* row = Eb + (size_t)t * EDIM;
        a0 = fmaf(w, row[tid +   0], a0);
        a1 = fmaf(w, row[tid + 256], a1);
        a2 = fmaf(w, row[tid + 512], a2);
        a3 = fmaf(w, row[tid + 768], a3);
    }
    float* ct = g_ct + (size_t)b * EDIM;
    ct[tid +   0] = a0;
    ct[tid + 256] = a1;
    ct[tid + 512] = a2;
    ct[tid + 768] = a3;
}

// ---------------- gates: z, r; store z and r*h ----------------
__global__ __launch_bounds__(256)
void gates_kernel(const float* __restrict__ h)
{
    const int idx = blockIdx.x * blockDim.x + threadIdx.x;
    if (idx >= BSZ * UDIM) return;
    const int m = idx >> 10;
    const int j = idx & 1023;
    const float* G1 = g_G1 + (size_t)m * 3 * UDIM;
    const float* G2 = g_G2 + (size_t)m * 2 * UDIM;
    float z = fminf(fmaxf(0.2f * (G1[j]        + G2[j])        + 0.5f, 0.f), 1.f);
    float r = fminf(fmaxf(0.2f * (G1[j + 1024] + G2[j + 1024]) + 0.5f, 0.f), 1.f);
    g_z[idx]  = z;
    g_rh[idx] = r * h[idx];   // Python: r*h@rh == (r*h)@rh
}

// ---------------- final: h_new -> out ----------------
__global__ __launch_bounds__(256)
void gru_final_kernel(const float* __restrict__ h, float* __restrict__ out)
{
    const int idx = blockIdx.x * blockDim.x + threadIdx.x;
    if (idx >= BSZ * UDIM) return;
    const int m = idx >> 10;
    const int j = idx & 1023;
    float hh = tanhf(g_G1[(size_t)m * 3 * UDIM + 2048 + j] + g_Ghh[idx]);
    float z  = g_z[idx];
    out[(size_t)m * 1088 + 64 + j] = z * h[idx] + (1.f - z) * hh;
}

// ---------------- launch ----------------
extern "C" void kernel_launch(void* const* d_in, const int* in_sizes, int n_in,
                              void* d_out, int out_size)
{
    (void)in_sizes; (void)n_in; (void)out_size;
    const float* inputs = (const float*)d_in[0];   // (512, 512)
    const float* h      = (const float*)d_in[1];   // (512, 1024)
    const float* E      = (const float*)d_in[2];   // (512, 64, 1024)
    const float* kern   = (const float*)d_in[3];   // (1536, 3072)
    const float* rker   = (const float*)d_in[4];   // (1024, 3072)
    const float* bias   = (const float*)d_in[5];   // (3072,)
    const float* Wa     = (const float*)d_in[6];   // (2048, 1024)
    const float* Va     = (const float*)d_in[7];   // (1024, 1)
    float* out = (float*)d_out;                    // (512, 1088)

    float *tanhE, *hWa, *epart, *ct, *G1, *G2, *rh, *Ghh;
    float *WaTlo, *WaThi, *kernT, *rkerT;
    cudaGetSymbolAddress((void**)&tanhE, g_tanhE);
    cudaGetSymbolAddress((void**)&hWa,   g_hWa);
    cudaGetSymbolAddress((void**)&epart, g_epart);
    cudaGetSymbolAddress((void**)&ct,    g_ct);
    cudaGetSymbolAddress((void**)&G1,    g_G1);
    cudaGetSymbolAddress((void**)&G2,    g_G2);
    cudaGetSymbolAddress((void**)&rh,    g_rh);
    cudaGetSymbolAddress((void**)&Ghh,   g_Ghh);
    cudaGetSymbolAddress((void**)&WaTlo, g_WaT_lo);
    cudaGetSymbolAddress((void**)&WaThi, g_WaT_hi);
    cudaGetSymbolAddress((void**)&kernT, g_kernT);
    cudaGetSymbolAddress((void**)&rkerT, g_rkerT);

    cudaFuncSetAttribute(tgemm_kernel<AM_TANH,   EP_STORE>, cudaFuncAttributeMaxDynamicSharedMemorySize, SM_TOTAL);
    cudaFuncSetAttribute(tgemm_kernel<AM_PLAIN,  EP_ATT  >, cudaFuncAttributeMaxDynamicSharedMemorySize, SM_TOTAL);
    cudaFuncSetAttribute(tgemm_kernel<AM_CONCAT, EP_BIAS >, cudaFuncAttributeMaxDynamicSharedMemorySize, SM_TOTAL);
    cudaFuncSetAttribute(tgemm_kernel<AM_PLAIN,  EP_STORE>, cudaFuncAttributeMaxDynamicSharedMemorySize, SM_TOTAL);

    dim3 t32(32, 8);
    // weight transposes (K-major B operands)
    transpose_kernel<<<dim3(32, 32), t32>>>(Wa,                 UDIM,        UDIM,        WaTlo);
    transpose_kernel<<<dim3(32, 32), t32>>>(Wa + UDIM * UDIM,   UDIM,        UDIM,        WaThi);
    transpose_kernel<<<dim3(96, 48), t32>>>(kern,               3 * UDIM,    XDIM + EDIM, kernT);
    transpose_kernel<<<dim3(96, 32), t32>>>(rker,               3 * UDIM,    UDIM,        rkerT);

    // tanh(E)
    const int n4 = BSZ * TLEN * EDIM / 4;
    tanh4_kernel<<<n4 / 256, 256>>>((const float4*)E, (float4*)tanhE, n4);

    // hWa = tanh(h) @ Wa[:U]                M=512  N=1024 K=1024
    tgemm_kernel<AM_TANH, EP_STORE><<<dim3(4, 4), 128, SM_TOTAL>>>(
        h, nullptr, UDIM, WaTlo, UDIM, 32, hWa, UDIM, nullptr, nullptr, nullptr);

    // attention GEMM + fused e-partials     M=32768 N=1024 K=1024
    tgemm_kernel<AM_PLAIN, EP_ATT><<<dim3(NBX_ATT, 256), 128, SM_TOTAL>>>(
        tanhE, nullptr, EDIM, WaThi, UDIM, 32, epart, 0, hWa, Va, nullptr);

    // softmax + alpha-out + context
    attn_kernel<<<BSZ, 256>>>(E, out);

    // G1 = [inputs|c_t] @ kernel + bias     M=512  N=3072 K=1536
    tgemm_kernel<AM_CONCAT, EP_BIAS><<<dim3(12, 4), 128, SM_TOTAL>>>(
        inputs, ct, 0, kernT, XDIM + EDIM, 48, G1, 3 * UDIM, nullptr, nullptr, bias);

    // G2 = h @ rker[:, :2048]               M=512  N=2048 K=1024
    tgemm_kernel<AM_PLAIN, EP_STORE><<<dim3(8, 4), 128, SM_TOTAL>>>(
        h, nullptr, UDIM, rkerT, UDIM, 32, G2, 2 * UDIM, nullptr, nullptr, nullptr);

    // gates
    gates_kernel<<<(BSZ * UDIM + 255) / 256, 256>>>(h);

    // Ghh = (r*h) @ rker[:, 2048:]          M=512  N=1024 K=1024
    tgemm_kernel<AM_PLAIN, EP_STORE><<<dim3(4, 4), 128, SM_TOTAL>>>(
        rh, nullptr, UDIM, rkerT + (size_t)2048 * UDIM, UDIM, 32, Ghh, UDIM, nullptr, nullptr, nullptr);

    // h_new
    gru_final_kernel<<<(BSZ * UDIM + 255) / 256, 256>>>(h, out);
}

// round 8
// speedup vs baseline: 3.0512x; 1.6926x over previous
#include <cuda_runtime.h>
#include <math.h>
#include <stdint.h>

#define BSZ  512
#define TLEN 64
#define XDIM 512
#define EDIM 1024
#define UDIM 1024
#define NBX_ATT 4          // N blocks of 256 in the attention GEMM (1024/256)

#define TM 128
#define TN 256
#define TK 32

#if defined(__CUDA_ARCH_FEAT_SM103_ALL) || defined(__CUDA_ARCH_FEAT_SM100_ALL) || defined(__CUDA_ARCH_FEAT_SM101_ALL)
#define HAS_TCGEN05 1
#else
#define HAS_TCGEN05 0
#endif

// ---------------- static scratch ----------------
__device__ float g_tanhE[(size_t)BSZ * TLEN * EDIM];          // 134 MB, tf32-rounded tanh(E)
__device__ float g_hWa  [(size_t)BSZ * UDIM];
__device__ float g_epart[(size_t)BSZ * TLEN * NBX_ATT];
__device__ float g_ct   [(size_t)BSZ * EDIM];
__device__ float g_G1   [(size_t)BSZ * 3 * UDIM];
__device__ float g_G2   [(size_t)BSZ * 2 * UDIM];
__device__ float g_z    [(size_t)BSZ * UDIM];
__device__ float g_rh   [(size_t)BSZ * UDIM];
__device__ float g_Ghh  [(size_t)BSZ * UDIM];
// K-major transposed, tf32-rounded weights: W_T[n][k]
__device__ float g_WaT_lo[(size_t)UDIM * UDIM];
__device__ float g_WaT_hi[(size_t)UDIM * UDIM];
__device__ float g_kernT [(size_t)3 * UDIM * (XDIM + EDIM)];
__device__ float g_rkerT [(size_t)3 * UDIM * UDIM];

// tf32 round (plain cvt, legal on all sm_80+ targets; used in prep kernels)
__device__ __forceinline__ uint32_t f2tf32(float f) {
    uint32_t r;
    asm("cvt.rna.tf32.f32 %0, %1;" : "=r"(r) : "f"(f));
    return r;
}

// ---------------- PTX helpers (sm_103a-only) ----------------
#if HAS_TCGEN05
__device__ __forceinline__ uint32_t smem_u32(const void* p) {
    uint32_t a;
    asm("{ .reg .u64 t; cvta.to.shared.u64 t, %1; cvt.u32.u64 %0, t; }" : "=r"(a) : "l"(p));
    return a;
}
#define SW128(x) ((x) ^ (((x) >> 3) & 0x70))

#define TCG_ALLOC(sm, n)  asm volatile("tcgen05.alloc.cta_group::1.sync.aligned.shared::cta.b32 [%0], %1;" :: "r"(sm), "r"(n) : "memory")
#define TCG_DEALLOC(t, n) asm volatile("tcgen05.dealloc.cta_group::1.sync.aligned.b32 %0, %1;" :: "r"(t), "r"(n))
#define TCG_RELINQ()      asm volatile("tcgen05.relinquish_alloc_permit.cta_group::1.sync.aligned;")
#define TCG_COMMIT(mb)    asm volatile("tcgen05.commit.cta_group::1.mbarrier::arrive::one.shared::cluster.b64 [%0];" :: "r"(mb) : "memory")
#define TCG_FENCE_AFTER() asm volatile("tcgen05.fence::after_thread_sync;" ::: "memory")
#define TCG_FENCE_BEFORE() asm volatile("tcgen05.fence::before_thread_sync;" ::: "memory")
#define TCG_WAIT_LD()     asm volatile("tcgen05.wait::ld.sync.aligned;" ::: "memory")
#define FENCE_ASYNC()     asm volatile("fence.proxy.async.shared::cta;" ::: "memory")
#define MBAR_INIT(mb, c)  asm volatile("mbarrier.init.shared.b64 [%0], %1;" :: "r"(mb), "r"(c) : "memory")

__device__ __forceinline__ void mbar_wait(uint32_t mb, uint32_t parity) {
    uint32_t done;
    asm volatile("{\n\t.reg .pred p;\n\t"
        "mbarrier.try_wait.parity.acquire.cta.shared::cta.b64 p, [%1], %2;\n\t"
        "selp.b32 %0, 1, 0, p;\n\t}"
        : "=r"(done) : "r"(mb), "r"(parity) : "memory");
    if (!done) {
        asm volatile("{\n\t.reg .pred P1;\n\t"
            "W_%=:\n\t"
            "mbarrier.try_wait.parity.acquire.cta.shared::cta.b64 P1, [%0], %1, 0x989680;\n\t"
            "@P1 bra.uni D_%=;\n\t"
            "bra.uni W_%=;\n\t"
            "D_%=:\n\t}"
            :: "r"(mb), "r"(parity) : "memory");
    }
}
__device__ __forceinline__ void mma_tf32_ss(uint32_t d, uint64_t ad, uint64_t bd,
                                            uint32_t idesc, uint32_t acc) {
    asm volatile("{\n\t.reg .pred p;\n\t"
        "setp.ne.u32 p, %5, 0;\n\t"
        "tcgen05.mma.cta_group::1.kind::tf32 [%0], %1, %2, %3, {%4, %4, %4, %4}, p;\n\t}"
        :: "r"(d), "l"(ad), "l"(bd), "r"(idesc), "r"(0u), "r"(acc) : "memory");
}
__device__ __forceinline__ void tmem_ld32(uint32_t* r, uint32_t a) {
    asm volatile("tcgen05.ld.sync.aligned.32x32b.x32.b32 "
        "{%0,%1,%2,%3,%4,%5,%6,%7,%8,%9,%10,%11,%12,%13,%14,%15,"
        "%16,%17,%18,%19,%20,%21,%22,%23,%24,%25,%26,%27,%28,%29,%30,%31}, [%32];"
        : "=r"(r[0]),"=r"(r[1]),"=r"(r[2]),"=r"(r[3]),"=r"(r[4]),"=r"(r[5]),"=r"(r[6]),"=r"(r[7]),
          "=r"(r[8]),"=r"(r[9]),"=r"(r[10]),"=r"(r[11]),"=r"(r[12]),"=r"(r[13]),"=r"(r[14]),"=r"(r[15]),
          "=r"(r[16]),"=r"(r[17]),"=r"(r[18]),"=r"(r[19]),"=r"(r[20]),"=r"(r[21]),"=r"(r[22]),"=r"(r[23]),
          "=r"(r[24]),"=r"(r[25]),"=r"(r[26]),"=r"(r[27]),"=r"(r[28]),"=r"(r[29]),"=r"(r[30]),"=r"(r[31])
        : "r"(a));
}
// SW128 K-major smem descriptor (LBO=1, SBO=64, version=1)
__device__ __forceinline__ uint64_t mk_desc(uint32_t addr) {
    const uint64_t base = (uint64_t(2) << 61) | (uint64_t(1) << 46)
                        | (uint64_t(64) << 32) | (uint64_t(1) << 16);
    return base | ((uint64_t)(addr >> 4) & 0x3FFF);
}
#endif // HAS_TCGEN05

// ---------------- tanh(E) precompute, tf32-rounded ----------------
__global__ void tanh4_kernel(const float4* __restrict__ in, float4* __restrict__ out, int n4)
{
    int i = blockIdx.x * blockDim.x + threadIdx.x;
    if (i < n4) {
        float4 v = in[i];
        uint4 u = make_uint4(f2tf32(tanhf(v.x)), f2tf32(tanhf(v.y)),
                             f2tf32(tanhf(v.z)), f2tf32(tanhf(v.w)));
        *reinterpret_cast<uint4*>(&out[i]) = u;
    }
}

// ---------------- fused transpose of all 4 weight matrices, tf32-rounded ----------------
// dst[n*K + k] = tf32(src[k*ld + n]); grid segments select matrix.
__global__ __launch_bounds__(256)
void transpose_all_kernel(const float* __restrict__ Wa, const float* __restrict__ kern,
                          const float* __restrict__ rker)
{
    const int bid = blockIdx.x;
    const float* src; float* dst; int ld, K, nb, kb;
    if (bid < 1024)      { src = Wa;                     dst = g_WaT_lo; ld = 1024; K = 1024; nb = bid & 31;  kb = bid >> 5; }
    else if (bid < 2048) { int b = bid - 1024; src = Wa + 1024 * 1024; dst = g_WaT_hi; ld = 1024; K = 1024; nb = b & 31; kb = b >> 5; }
    else if (bid < 6656) { int b = bid - 2048; src = kern; dst = g_kernT; ld = 3072; K = 1536; nb = b % 96; kb = b / 96; }
    else                 { int b = bid - 6656; src = rker; dst = g_rkerT; ld = 3072; K = 1024; nb = b % 96; kb = b / 96; }

    __shared__ float t[32][33];
    const int tx = threadIdx.x, ty = threadIdx.y;
    const int n0 = nb * 32, k0 = kb * 32;
    #pragma unroll
    for (int i = 0; i < 32; i += 8)
        t[ty + i][tx] = src[(size_t)(k0 + ty + i) * ld + n0 + tx];
    __syncthreads();
    #pragma unroll
    for (int i = 0; i < 32; i += 8)
        dst[(size_t)(n0 + ty + i) * K + k0 + tx] = __uint_as_float(f2tf32(t[tx][ty + i]));
}

// ---------------- GEMM: 128x256 tile, 256 threads ----------------
enum { AM_PLAIN = 0, AM_TANH = 1, AM_CONCAT = 2 };
enum { EP_STORE = 0, EP_BIAS = 1, EP_ATT = 2 };

#define SM_A0   0
#define SM_A1   16384
#define SM_B0   32768
#define SM_B1   65536
#define SM_CTRL 98304         // [tmem_ptr:4][pad:4][mbar0:8][mbar1:8]
#define SM_TOTAL (98304 + 128)

template<int AMODE, int APRE, int EMODE>
__global__ __launch_bounds__(256)
void tgemm_kernel(const float* __restrict__ A0, const float* __restrict__ A1, int lda,
                  const float* __restrict__ Bt, int ldb, int nK,
                  float* __restrict__ C, int ldc,
                  const float* __restrict__ hWa, const float* __restrict__ Va,
                  const float* __restrict__ bias)
{
    extern __shared__ char smc[];
    const int tid = threadIdx.x;
    const int row0 = blockIdx.y * TM;
    const int col0 = blockIdx.x * TN;

#if HAS_TCGEN05
    const uint32_t sb  = smem_u32(smc);
    const int wid = tid >> 5;
    const int lid = tid & 31;

    if (wid == 0) { TCG_ALLOC(sb + SM_CTRL, TN); TCG_RELINQ(); }
    if (tid == 0) { MBAR_INIT(sb + SM_CTRL + 8, 1); MBAR_INIT(sb + SM_CTRL + 16, 1); }
    __syncthreads();
    uint32_t tmem;
    asm volatile("ld.shared.b32 %0, [%1];" : "=r"(tmem) : "r"(sb + SM_CTRL));

    const uint32_t idesc = (1u << 4) | (2u << 7) | (2u << 10)
                         | ((TN / 8) << 17) | ((TM / 16) << 24);

    // per-thread load slots: A = 4 float4, B = 8 float4
    int ar[4], aq[4], br8[8], bq8[8];
    #pragma unroll
    for (int i = 0; i < 4; ++i) { const int s = i * 256 + tid; ar[i] = s >> 3; aq[i] = s & 7; }
    #pragma unroll
    for (int i = 0; i < 8; ++i) { const int s = i * 256 + tid; br8[i] = s >> 3; bq8[i] = s & 7; }

    int ph0 = 0, ph1 = 0;
    for (int kt = 0; kt < nK; ++kt) {
        const int buf = kt & 1;
        if (kt >= 2) {
            if (buf == 0) { mbar_wait(sb + SM_CTRL + 8,  ph0); ph0 ^= 1; }
            else          { mbar_wait(sb + SM_CTRL + 16, ph1); ph1 ^= 1; }
        }
        const int k0 = kt * TK;

        // ---- batch ALL gmem loads first (12 independent LDG.128) ----
        float4 av[4], bv[8];
        #pragma unroll
        for (int i = 0; i < 4; ++i) {
            const int r = ar[i];
            if (AMODE == AM_CONCAT) {
                if (k0 < XDIM)
                    av[i] = *reinterpret_cast<const float4*>(&A0[(size_t)(row0 + r) * XDIM + k0 + aq[i] * 4]);
                else
                    av[i] = *reinterpret_cast<const float4*>(&A1[(size_t)(row0 + r) * EDIM + (k0 - XDIM) + aq[i] * 4]);
            } else {
                av[i] = *reinterpret_cast<const float4*>(&A0[(size_t)(row0 + r) * lda + k0 + aq[i] * 4]);
            }
        }
        #pragma unroll
        for (int i = 0; i < 8; ++i)
            bv[i] = *reinterpret_cast<const float4*>(&Bt[(size_t)(col0 + br8[i]) * ldb + k0 + bq8[i] * 4]);

        // ---- then all smem stores ----
        char* abase = smc + (buf ? SM_A1 : SM_A0);
        char* bbase = smc + (buf ? SM_B1 : SM_B0);
        #pragma unroll
        for (int i = 0; i < 4; ++i) {
            float4 v = av[i];
            if (AMODE == AM_TANH) {
                v.x = tanhf(v.x); v.y = tanhf(v.y); v.z = tanhf(v.z); v.w = tanhf(v.w);
            }
            uint4 u;
            if (APRE) u = *reinterpret_cast<uint4*>(&v);       // pre-rounded, raw bits
            else      u = make_uint4(f2tf32(v.x), f2tf32(v.y), f2tf32(v.z), f2tf32(v.w));
            *reinterpret_cast<uint4*>(abase + SW128(ar[i] * 128 + aq[i] * 16)) = u;
        }
        #pragma unroll
        for (int i = 0; i < 8; ++i)                             // B always pre-rounded
            *reinterpret_cast<uint4*>(bbase + SW128(br8[i] * 128 + bq8[i] * 16)) =
                *reinterpret_cast<uint4*>(&bv[i]);
        __syncthreads();

        if (tid == 0) {
            FENCE_ASYNC();
            const uint64_t ad = mk_desc(sb + (buf ? SM_A1 : SM_A0));
            const uint64_t bd = mk_desc(sb + (buf ? SM_B1 : SM_B0));
            #pragma unroll
            for (int s = 0; s < 4; ++s)
                mma_tf32_ss(tmem, ad + s * 2, bd + s * 2, idesc, (kt > 0 || s > 0) ? 1u : 0u);
            TCG_COMMIT(sb + SM_CTRL + 8 + buf * 8);
        }
    }
    {
        const int lb = (nK - 1) & 1;
        mbar_wait(sb + SM_CTRL + 8 + lb * 8, lb == 0 ? ph0 : ph1);
    }
    TCG_FENCE_AFTER();

    // ---- epilogue: 8 warps, two column halves ----
    const int sp = wid & 3;            // TMEM subpartition (M rows)
    const int hf = wid >> 2;           // column half
    const int m  = row0 + sp * 32 + lid;

    if (EMODE == EP_ATT) {
        const int b = m >> 6;
        const float* hrow = hWa + (size_t)b * UDIM;
        float s = 0.f;
        #pragma unroll
        for (int c = 0; c < 4; ++c) {
            const int cc = hf * 4 + c;
            uint32_t regs[32];
            tmem_ld32(regs, tmem + cc * 32);
            TCG_WAIT_LD();
            const int jj0 = col0 + cc * 32;
            #pragma unroll
            for (int j = 0; j < 32; ++j)
                s += tanhf(__uint_as_float(regs[j]) + hrow[jj0 + j]) * Va[jj0 + j];
        }
        float* sm = reinterpret_cast<float*>(smc);
        sm[wid * 32 + lid] = s;
        __syncthreads();
        if (wid < 4)
            C[(size_t)m * NBX_ATT + blockIdx.x] = sm[wid * 32 + lid] + sm[(wid + 4) * 32 + lid];
    } else {
        #pragma unroll
        for (int c = 0; c < 4; ++c) {
            const int cc = hf * 4 + c;
            uint32_t regs[32];
            tmem_ld32(regs, tmem + cc * 32);
            TCG_WAIT_LD();
            const int jj0 = col0 + cc * 32;
            #pragma unroll
            for (int j = 0; j < 32; j += 4) {
                float4 o;
                o.x = __uint_as_float(regs[j + 0]);
                o.y = __uint_as_float(regs[j + 1]);
                o.z = __uint_as_float(regs[j + 2]);
                o.w = __uint_as_float(regs[j + 3]);
                if (EMODE == EP_BIAS) {
                    o.x += bias[jj0 + j + 0]; o.y += bias[jj0 + j + 1];
                    o.z += bias[jj0 + j + 2]; o.w += bias[jj0 + j + 3];
                }
                *reinterpret_cast<float4*>(&C[(size_t)m * ldc + jj0 + j]) = o;
            }
        }
    }
    TCG_FENCE_BEFORE();
    __syncthreads();
    if (wid == 0) TCG_DEALLOC(tmem, TN);

#else
    // ============ FFMA fallback (plain-sm_103 pass; dead on GB300) ============
    float* Bs = reinterpret_cast<float*>(smc);       // 32 x 64 tile of B
    const int Ktot = nK * TK;
    const int mt = tid & 127;
    const int m = row0 + mt;
    float s_att = 0.f;

    for (int nc = 0; nc < 4; ++nc) {
        float acc[64];
        #pragma unroll
        for (int j = 0; j < 64; ++j) acc[j] = 0.f;

        for (int kt = 0; kt < Ktot; kt += 32) {
            for (int i = tid; i < 32 * 64; i += 256) {
                const int kk = i & 31, j = i >> 5;
                Bs[kk * 64 + j] = Bt[(size_t)(col0 + nc * 64 + j) * ldb + kt + kk];
            }
            __syncthreads();
            if (tid < 128) {
                float av[32];
                #pragma unroll
                for (int q = 0; q < 32; q += 4) {
                    const int k4 = kt + q;
                    float4 v;
                    if (AMODE == AM_CONCAT) {
                        if (k4 < XDIM)
                            v = *reinterpret_cast<const float4*>(&A0[(size_t)m * XDIM + k4]);
                        else
                            v = *reinterpret_cast<const float4*>(&A1[(size_t)m * EDIM + (k4 - XDIM)]);
                    } else {
                        v = *reinterpret_cast<const float4*>(&A0[(size_t)m * lda + k4]);
                        if (AMODE == AM_TANH) {
                            v.x = tanhf(v.x); v.y = tanhf(v.y); v.z = tanhf(v.z); v.w = tanhf(v.w);
                        }
                    }
                    av[q] = v.x; av[q + 1] = v.y; av[q + 2] = v.z; av[q + 3] = v.w;
                }
                #pragma unroll 4
                for (int kk = 0; kk < 32; ++kk) {
                    const float a = av[kk];
                    #pragma unroll
                    for (int j = 0; j < 64; ++j)
                        acc[j] = fmaf(a, Bs[kk * 64 + j], acc[j]);
                }
            }
            __syncthreads();
        }
        if (tid < 128) {
            const int jj0 = col0 + nc * 64;
            if (EMODE == EP_ATT) {
                const int b = m >> 6;
                for (int j = 0; j < 64; ++j)
                    s_att += tanhf(acc[j] + hWa[(size_t)b * UDIM + jj0 + j]) * Va[jj0 + j];
            } else {
                for (int j = 0; j < 64; ++j) {
                    float o = acc[j];
                    if (EMODE == EP_BIAS) o += bias[jj0 + j];
                    C[(size_t)m * ldc + jj0 + j] = o;
                }
            }
        }
    }
    if (EMODE == EP_ATT && tid < 128)
        C[(size_t)m * NBX_ATT + blockIdx.x] = s_att;
#endif
}

// ---------------- softmax over T + context; writes alpha to out ----------------
__global__ __launch_bounds__(256)
void attn_kernel(const float* __restrict__ E, float* __restrict__ out)
{
    const int b   = blockIdx.x;
    const int tid = threadIdx.x;
    __shared__ float alpha[TLEN];

    if (tid < TLEN) {
        const float* ep = g_epart + (size_t)(b * TLEN + tid) * NBX_ATT;
        float e = 0.f;
        #pragma unroll
        for (int p = 0; p < NBX_ATT; ++p) e += ep[p];
        alpha[tid] = e;
    }
    __syncthreads();
    if (tid < 32) {
        float v0 = alpha[tid], v1 = alpha[tid + 32];
        float mx = fmaxf(v0, v1);
        #pragma unroll
        for (int off = 16; off > 0; off >>= 1)
            mx = fmaxf(mx, __shfl_xor_sync(0xffffffffu, mx, off));
        float e0 = expf(v0 - mx), e1 = expf(v1 - mx);
        float s = e0 + e1;
        #pragma unroll
        for (int off = 16; off > 0; off >>= 1)
            s += __shfl_xor_sync(0xffffffffu, s, off);
        float inv = 1.f / s;
        alpha[tid]      = e0 * inv;
        alpha[tid + 32] = e1 * inv;
    }
    __syncthreads();
    if (tid < TLEN)
        out[(size_t)b * 1088 + tid] = alpha[tid];

    const float* Eb = E + (size_t)b * TLEN * EDIM;
    float a0 = 0.f, a1 = 0.f, a2 = 0.f, a3 = 0.f;
    for (int t = 0; t < TLEN; ++t) {
        const float w = alpha[t];
        const float* row = Eb + (size_t)t * EDIM;
        a0 = fmaf(w, row[tid +   0], a0);
        a1 = fmaf(w, row[tid + 256], a1);
        a2 = fmaf(w, row[tid + 512], a2);
        a3 = fmaf(w, row[tid + 768], a3);
    }
    float* ct = g_ct + (size_t)b * EDIM;
    ct[tid +   0] = a0;
    ct[tid + 256] = a1;
    ct[tid + 512] = a2;
    ct[tid + 768] = a3;
}

// ---------------- gates: z, r; store z and r*h ----------------
__global__ __launch_bounds__(256)
void gates_kernel(const float* __restrict__ h)
{
    const int idx = blockIdx.x * blockDim.x + threadIdx.x;
    if (idx >= BSZ * UDIM) return;
    const int m = idx >> 10;
    const int j = idx & 1023;
    const float* G1 = g_G1 + (size_t)m * 3 * UDIM;
    const float* G2 = g_G2 + (size_t)m * 2 * UDIM;
    float z = fminf(fmaxf(0.2f * (G1[j]        + G2[j])        + 0.5f, 0.f), 1.f);
    float r = fminf(fmaxf(0.2f * (G1[j + 1024] + G2[j + 1024]) + 0.5f, 0.f), 1.f);
    g_z[idx]  = z;
    g_rh[idx] = r * h[idx];   // Python: r*h@rh == (r*h)@rh
}

// ---------------- final: h_new -> out ----------------
__global__ __launch_bounds__(256)
void gru_final_kernel(const float* __restrict__ h, float* __restrict__ out)
{
    const int idx = blockIdx.x * blockDim.x + threadIdx.x;
    if (idx >= BSZ * UDIM) return;
    const int m = idx >> 10;
    const int j = idx & 1023;
    float hh = tanhf(g_G1[(size_t)m * 3 * UDIM + 2048 + j] + g_Ghh[idx]);
    float z  = g_z[idx];
    out[(size_t)m * 1088 + 64 + j] = z * h[idx] + (1.f - z) * hh;
}

// ---------------- launch ----------------
extern "C" void kernel_launch(void* const* d_in, const int* in_sizes, int n_in,
                              void* d_out, int out_size)
{
    (void)in_sizes; (void)n_in; (void)out_size;
    const float* inputs = (const float*)d_in[0];   // (512, 512)
    const float* h      = (const float*)d_in[1];   // (512, 1024)
    const float* E      = (const float*)d_in[2];   // (512, 64, 1024)
    const float* kern   = (const float*)d_in[3];   // (1536, 3072)
    const float* rker   = (const float*)d_in[4];   // (1024, 3072)
    const float* bias   = (const float*)d_in[5];   // (3072,)
    const float* Wa     = (const float*)d_in[6];   // (2048, 1024)
    const float* Va     = (const float*)d_in[7];   // (1024, 1)
    float* out = (float*)d_out;                    // (512, 1088)

    float *tanhE, *hWa, *epart, *ct, *G1, *G2, *rh, *Ghh;
    float *WaTlo, *WaThi, *kernT, *rkerT;
    cudaGetSymbolAddress((void**)&tanhE, g_tanhE);
    cudaGetSymbolAddress((void**)&hWa,   g_hWa);
    cudaGetSymbolAddress((void**)&epart, g_epart);
    cudaGetSymbolAddress((void**)&ct,    g_ct);
    cudaGetSymbolAddress((void**)&G1,    g_G1);
    cudaGetSymbolAddress((void**)&G2,    g_G2);
    cudaGetSymbolAddress((void**)&rh,    g_rh);
    cudaGetSymbolAddress((void**)&Ghh,   g_Ghh);
    cudaGetSymbolAddress((void**)&WaTlo, g_WaT_lo);
    cudaGetSymbolAddress((void**)&WaThi, g_WaT_hi);
    cudaGetSymbolAddress((void**)&kernT, g_kernT);
    cudaGetSymbolAddress((void**)&rkerT, g_rkerT);

    cudaFuncSetAttribute(tgemm_kernel<AM_TANH,   0, EP_STORE>, cudaFuncAttributeMaxDynamicSharedMemorySize, SM_TOTAL);
    cudaFuncSetAttribute(tgemm_kernel<AM_PLAIN,  1, EP_ATT  >, cudaFuncAttributeMaxDynamicSharedMemorySize, SM_TOTAL);
    cudaFuncSetAttribute(tgemm_kernel<AM_CONCAT, 0, EP_BIAS >, cudaFuncAttributeMaxDynamicSharedMemorySize, SM_TOTAL);
    cudaFuncSetAttribute(tgemm_kernel<AM_PLAIN,  0, EP_STORE>, cudaFuncAttributeMaxDynamicSharedMemorySize, SM_TOTAL);

    // [0] all weight transposes (tf32-rounded)
    transpose_all_kernel<<<9728, dim3(32, 8)>>>(Wa, kern, rker);

    // [1] tanh(E), tf32-rounded
    const int n4 = BSZ * TLEN * EDIM / 4;
    tanh4_kernel<<<n4 / 256, 256>>>((const float4*)E, (float4*)tanhE, n4);

    // [2] hWa = tanh(h) @ Wa[:U]            M=512  N=1024 K=1024
    tgemm_kernel<AM_TANH, 0, EP_STORE><<<dim3(4, 4), 256, SM_TOTAL>>>(
        h, nullptr, UDIM, WaTlo, UDIM, 32, hWa, UDIM, nullptr, nullptr, nullptr);

    // [3] attention GEMM + fused e-partials  M=32768 N=1024 K=1024
    tgemm_kernel<AM_PLAIN, 1, EP_ATT><<<dim3(NBX_ATT, 256), 256, SM_TOTAL>>>(
        tanhE, nullptr, EDIM, WaThi, UDIM, 32, epart, 0, hWa, Va, nullptr);

    // [4] softmax + alpha-out + context
    attn_kernel<<<BSZ, 256>>>(E, out);

    // [5] G1 = [inputs|c_t] @ kernel + bias  M=512  N=3072 K=1536
    tgemm_kernel<AM_CONCAT, 0, EP_BIAS><<<dim3(12, 4), 256, SM_TOTAL>>>(
        inputs, ct, 0, kernT, XDIM + EDIM, 48, G1, 3 * UDIM, nullptr, nullptr, bias);

    // [6] G2 = h @ rker[:, :2048]            M=512  N=2048 K=1024
    tgemm_kernel<AM_PLAIN, 0, EP_STORE><<<dim3(8, 4), 256, SM_TOTAL>>>(
        h, nullptr, UDIM, rkerT, UDIM, 32, G2, 2 * UDIM, nullptr, nullptr, nullptr);

    // [7] gates
    gates_kernel<<<(BSZ * UDIM + 255) / 256, 256>>>(h);

    // [8] Ghh = (r*h) @ rker[:, 2048:]       M=512  N=1024 K=1024
    tgemm_kernel<AM_PLAIN, 0, EP_STORE><<<dim3(4, 4), 256, SM_TOTAL>>>(
        rh, nullptr, UDIM, rkerT + (size_t)2048 * UDIM, UDIM, 32, Ghh, UDIM, nullptr, nullptr, nullptr);

    // [9] h_new
    gru_final_kernel<<<(BSZ * UDIM + 255) / 256, 256>>>(h, out);
}

// round 10
// speedup vs baseline: 6.3290x; 2.0742x over previous
#include <cuda_runtime.h>
#include <math.h>
#include <stdint.h>

#define BSZ  512
#define TLEN 64
#define XDIM 512
#define EDIM 1024
#define UDIM 1024
#define NBX_ATT 4          // N blocks of 256 in the attention GEMM (1024/256)

#define TM 128
#define TN 256
#define TK 32
#define NSTAGE 4

#if defined(__CUDA_ARCH_FEAT_SM103_ALL) || defined(__CUDA_ARCH_FEAT_SM100_ALL) || defined(__CUDA_ARCH_FEAT_SM101_ALL)
#define HAS_TCGEN05 1
#else
#define HAS_TCGEN05 0
#endif

// ---------------- static scratch ----------------
__device__ float g_tanhE [(size_t)BSZ * TLEN * EDIM];         // tf32-rounded tanh(E)
__device__ float g_tanh_h[(size_t)BSZ * UDIM];                // tf32(tanh(h))
__device__ float g_h32   [(size_t)BSZ * UDIM];                // tf32(h)
__device__ float g_x     [(size_t)BSZ * (XDIM + EDIM)];       // tf32([inputs | c_t])
__device__ float g_hWa   [(size_t)BSZ * UDIM];
__device__ float g_epart [(size_t)BSZ * TLEN * NBX_ATT];
__device__ float g_G1    [(size_t)BSZ * 3 * UDIM];
__device__ float g_G2    [(size_t)BSZ * 2 * UDIM];
__device__ float g_z     [(size_t)BSZ * UDIM];
__device__ float g_rh    [(size_t)BSZ * UDIM];                // tf32(r*h)
__device__ float g_Ghh   [(size_t)BSZ * UDIM];
// K-major transposed, tf32-rounded weights: W_T[n][k]
__device__ float g_WaT_lo[(size_t)UDIM * UDIM];
__device__ float g_WaT_hi[(size_t)UDIM * UDIM];
__device__ float g_kernT [(size_t)3 * UDIM * (XDIM + EDIM)];
__device__ float g_rkerT [(size_t)3 * UDIM * UDIM];

// tf32 round (valid on all sm_80+ targets; used in prep kernels)
__device__ __forceinline__ uint32_t f2tf32(float f) {
    uint32_t r;
    asm("cvt.rna.tf32.f32 %0, %1;" : "=r"(r) : "f"(f));
    return r;
}
__device__ __forceinline__ float tf32r(float f) { return __uint_as_float(f2tf32(f)); }

// ---------------- PTX helpers (sm_103a-only) ----------------
#if HAS_TCGEN05
__device__ __forceinline__ uint32_t smem_u32(const void* p) {
    uint32_t a;
    asm("{ .reg .u64 t; cvta.to.shared.u64 t, %1; cvt.u32.u64 %0, t; }" : "=r"(a) : "l"(p));
    return a;
}
#define SW128(x) ((x) ^ (((x) >> 3) & 0x70))

#define TCG_ALLOC(sm, n)  asm volatile("tcgen05.alloc.cta_group::1.sync.aligned.shared::cta.b32 [%0], %1;" :: "r"(sm), "r"(n) : "memory")
#define TCG_DEALLOC(t, n) asm volatile("tcgen05.dealloc.cta_group::1.sync.aligned.b32 %0, %1;" :: "r"(t), "r"(n))
#define TCG_RELINQ()      asm volatile("tcgen05.relinquish_alloc_permit.cta_group::1.sync.aligned;")
#define TCG_COMMIT(mb)    asm volatile("tcgen05.commit.cta_group::1.mbarrier::arrive::one.shared::cluster.b64 [%0];" :: "r"(mb) : "memory")
#define TCG_FENCE_AFTER() asm volatile("tcgen05.fence::after_thread_sync;" ::: "memory")
#define TCG_FENCE_BEFORE() asm volatile("tcgen05.fence::before_thread_sync;" ::: "memory")
#define TCG_WAIT_LD()     asm volatile("tcgen05.wait::ld.sync.aligned;" ::: "memory")
#define FENCE_ASYNC()     asm volatile("fence.proxy.async.shared::cta;" ::: "memory")
#define MBAR_INIT(mb, c)  asm volatile("mbarrier.init.shared.b64 [%0], %1;" :: "r"(mb), "r"(c) : "memory")
#define CP_ASYNC16(dst, src) asm volatile("cp.async.cg.shared.global [%0], [%1], 16;" :: "r"(dst), "l"(src) : "memory")
#define CP_COMMIT()       asm volatile("cp.async.commit_group;" ::: "memory")
#define CP_WAIT(n)        asm volatile("cp.async.wait_group %0;" :: "n"(n) : "memory")

__device__ __forceinline__ void mbar_wait(uint32_t mb, uint32_t parity) {
    uint32_t done;
    asm volatile("{\n\t.reg .pred p;\n\t"
        "mbarrier.try_wait.parity.acquire.cta.shared::cta.b64 p, [%1], %2;\n\t"
        "selp.b32 %0, 1, 0, p;\n\t}"
        : "=r"(done) : "r"(mb), "r"(parity) : "memory");
    if (!done) {
        asm volatile("{\n\t.reg .pred P1;\n\t"
            "W_%=:\n\t"
            "mbarrier.try_wait.parity.acquire.cta.shared::cta.b64 P1, [%0], %1, 0x989680;\n\t"
            "@P1 bra.uni D_%=;\n\t"
            "bra.uni W_%=;\n\t"
            "D_%=:\n\t}"
            :: "r"(mb), "r"(parity) : "memory");
    }
}
__device__ __forceinline__ void mma_tf32_ss(uint32_t d, uint64_t ad, uint64_t bd,
                                            uint32_t idesc, uint32_t acc) {
    asm volatile("{\n\t.reg .pred p;\n\t"
        "setp.ne.u32 p, %5, 0;\n\t"
        "tcgen05.mma.cta_group::1.kind::tf32 [%0], %1, %2, %3, {%4, %4, %4, %4}, p;\n\t}"
        :: "r"(d), "l"(ad), "l"(bd), "r"(idesc), "r"(0u), "r"(acc) : "memory");
}
__device__ __forceinline__ void tmem_ld32(uint32_t* r, uint32_t a) {
    asm volatile("tcgen05.ld.sync.aligned.32x32b.x32.b32 "
        "{%0,%1,%2,%3,%4,%5,%6,%7,%8,%9,%10,%11,%12,%13,%14,%15,"
        "%16,%17,%18,%19,%20,%21,%22,%23,%24,%25,%26,%27,%28,%29,%30,%31}, [%32];"
        : "=r"(r[0]),"=r"(r[1]),"=r"(r[2]),"=r"(r[3]),"=r"(r[4]),"=r"(r[5]),"=r"(r[6]),"=r"(r[7]),
          "=r"(r[8]),"=r"(r[9]),"=r"(r[10]),"=r"(r[11]),"=r"(r[12]),"=r"(r[13]),"=r"(r[14]),"=r"(r[15]),
          "=r"(r[16]),"=r"(r[17]),"=r"(r[18]),"=r"(r[19]),"=r"(r[20]),"=r"(r[21]),"=r"(r[22]),"=r"(r[23]),
          "=r"(r[24]),"=r"(r[25]),"=r"(r[26]),"=r"(r[27]),"=r"(r[28]),"=r"(r[29]),"=r"(r[30]),"=r"(r[31])
        : "r"(a));
}
// SW128 K-major smem descriptor (LBO=1, SBO=64, version=1)
__device__ __forceinline__ uint64_t mk_desc(uint32_t addr) {
    const uint64_t base = (uint64_t(2) << 61) | (uint64_t(1) << 46)
                        | (uint64_t(64) << 32) | (uint64_t(1) << 16);
    return base | ((uint64_t)(addr >> 4) & 0x3FFF);
}
#endif // HAS_TCGEN05

// ---------------- tanh(E) precompute, tf32-rounded ----------------
__global__ void tanh4_kernel(const float4* __restrict__ in, float4* __restrict__ out, int n4)
{
    int i = blockIdx.x * blockDim.x + threadIdx.x;
    if (i < n4) {
        float4 v = in[i];
        uint4 u = make_uint4(f2tf32(tanhf(v.x)), f2tf32(tanhf(v.y)),
                             f2tf32(tanhf(v.z)), f2tf32(tanhf(v.w)));
        *reinterpret_cast<uint4*>(&out[i]) = u;
    }
}

// ---------------- prep: tf32(h), tf32(tanh(h)), g_x[:, :512] = tf32(inputs) ----------------
__global__ void prep_kernel(const float* __restrict__ h, const float* __restrict__ inputs)
{
    const int idx = blockIdx.x * blockDim.x + threadIdx.x;
    if (idx < BSZ * UDIM) {
        float v = h[idx];
        g_h32[idx]    = tf32r(v);
        g_tanh_h[idx] = tf32r(tanhf(v));
    }
    if (idx < BSZ * XDIM) {
        const int m = idx >> 9, j = idx & 511;
        g_x[(size_t)m * (XDIM + EDIM) + j] = tf32r(inputs[idx]);
    }
}

// ---------------- fused transpose of all 4 weight matrices, tf32-rounded ----------------
__global__ __launch_bounds__(256)
void transpose_all_kernel(const float* __restrict__ Wa, const float* __restrict__ kern,
                          const float* __restrict__ rker)
{
    const int bid = blockIdx.x;
    const float* src; float* dst; int ld, K, nb, kb;
    if (bid < 1024)      { src = Wa;                     dst = g_WaT_lo; ld = 1024; K = 1024; nb = bid & 31;  kb = bid >> 5; }
    else if (bid < 2048) { int b = bid - 1024; src = Wa + 1024 * 1024; dst = g_WaT_hi; ld = 1024; K = 1024; nb = b & 31; kb = b >> 5; }
    else if (bid < 6656) { int b = bid - 2048; src = kern; dst = g_kernT; ld = 3072; K = 1536; nb = b % 96; kb = b / 96; }
    else                 { int b = bid - 6656; src = rker; dst = g_rkerT; ld = 3072; K = 1024; nb = b % 96; kb = b / 96; }

    __shared__ float t[32][33];
    const int tx = threadIdx.x, ty = threadIdx.y;
    const int n0 = nb * 32, k0 = kb * 32;
    #pragma unroll
    for (int i = 0; i < 32; i += 8)
        t[ty + i][tx] = src[(size_t)(k0 + ty + i) * ld + n0 + tx];
    __syncthreads();
    #pragma unroll
    for (int i = 0; i < 32; i += 8)
        dst[(size_t)(n0 + ty + i) * K + k0 + tx] = tf32r(t[tx][ty + i]);
}

// ---------------- GEMM: 128x256 tile, cp.async 4-stage pipeline ----------------
enum { EP_STORE = 0, EP_BIAS = 1, EP_ATT = 2 };

#define SM_STAGE_BYTES 49152              // A 16KB + B 32KB
#define SM_CTRL (NSTAGE * SM_STAGE_BYTES) // 196608: [tmem_ptr:8][mbar x4: 8 each]
#define SM_TOTAL (SM_CTRL + 64)

template<int EMODE>
__global__ __launch_bounds__(256)
void tgemm_kernel(const float* __restrict__ A, int lda,
                  const float* __restrict__ Bt, int ldb, int nK,
                  float* __restrict__ C, int ldc,
                  const float* __restrict__ hWa, const float* __restrict__ Va,
                  const float* __restrict__ bias)
{
    extern __shared__ char smc[];
    const int tid = threadIdx.x;
    const int row0 = blockIdx.y * TM;
    const int col0 = blockIdx.x * TN;

#if HAS_TCGEN05
    const uint32_t sb  = smem_u32(smc);
    const int wid = tid >> 5;
    const int lid = tid & 31;

    if (wid == 0) { TCG_ALLOC(sb + SM_CTRL, TN); TCG_RELINQ(); }
    if (tid == 0) {
        #pragma unroll
        for (int s = 0; s < NSTAGE; ++s) MBAR_INIT(sb + SM_CTRL + 8 + 8 * s, 1);
    }
    __syncthreads();
    uint32_t tmem;
    asm volatile("ld.shared.b32 %0, [%1];" : "=r"(tmem) : "r"(sb + SM_CTRL));

    const uint32_t idesc = (1u << 4) | (2u << 7) | (2u << 10)
                         | ((TN / 8) << 17) | ((TM / 16) << 24);

    // per-thread cp.async slots: A = 4 x 16B, B = 8 x 16B
    int ar[4], aq[4], br8[8], bq8[8];
    #pragma unroll
    for (int i = 0; i < 4; ++i) { const int s = i * 256 + tid; ar[i] = s >> 3; aq[i] = s & 7; }
    #pragma unroll
    for (int i = 0; i < 8; ++i) { const int s = i * 256 + tid; br8[i] = s >> 3; bq8[i] = s & 7; }

    uint32_t phbits = 0;   // per-stage wait-parity bits
    const int itMax = nK + NSTAGE - 1;
    for (int it = 0; it < itMax; ++it) {
        // -------- producer: stage it --------
        if (it < nK) {
            const int s = it & (NSTAGE - 1);
            if (it >= NSTAGE) {
                mbar_wait(sb + SM_CTRL + 8 + 8 * s, (phbits >> s) & 1u);
                phbits ^= 1u << s;
            }
            const int k0 = it * TK;
            const uint32_t sA = sb + s * SM_STAGE_BYTES;
            const uint32_t sB = sA + 16384;
            #pragma unroll
            for (int i = 0; i < 4; ++i)
                CP_ASYNC16(sA + SW128(ar[i] * 128 + aq[i] * 16),
                           &A[(size_t)(row0 + ar[i]) * lda + k0 + aq[i] * 4]);
            #pragma unroll
            for (int i = 0; i < 8; ++i)
                CP_ASYNC16(sB + SW128(br8[i] * 128 + bq8[i] * 16),
                           &Bt[(size_t)(col0 + br8[i]) * ldb + k0 + bq8[i] * 4]);
        }
        CP_COMMIT();   // one group per iteration (empty in tail) keeps wait-count static

        // -------- consumer: chunk j = it - (NSTAGE-1) --------
        const int j = it - (NSTAGE - 1);
        if (j >= 0) {
            CP_WAIT(NSTAGE - 1);       // group j landed
            __syncthreads();           // all threads' copies visible to async proxy
            if (tid == 0) {
                FENCE_ASYNC();
                const int s = j & (NSTAGE - 1);
                const uint64_t ad = mk_desc(sb + s * SM_STAGE_BYTES);
                const uint64_t bd = mk_desc(sb + s * SM_STAGE_BYTES + 16384);
                #pragma unroll
                for (int ss = 0; ss < 4; ++ss)
                    mma_tf32_ss(tmem, ad + ss * 2, bd + ss * 2, idesc, (j > 0 || ss > 0) ? 1u : 0u);
                TCG_COMMIT(sb + SM_CTRL + 8 + 8 * s);
            }
        }
    }
    {   // wait for the final MMA (in-order completion covers all earlier chunks)
        const int sl = (nK - 1) & (NSTAGE - 1);
        mbar_wait(sb + SM_CTRL + 8 + 8 * sl, (phbits >> sl) & 1u);
    }
    TCG_FENCE_AFTER();

    // ---- epilogue: 8 warps, two column halves ----
    const int sp = wid & 3;            // TMEM subpartition (M rows)
    const int hf = wid >> 2;           // column half
    const int m  = row0 + sp * 32 + lid;

    if (EMODE == EP_ATT) {
        const int b = m >> 6;
        const float* hrow = hWa + (size_t)b * UDIM;
        float s = 0.f;
        #pragma unroll
        for (int c = 0; c < 4; ++c) {
            const int cc = hf * 4 + c;
            uint32_t regs[32];
            tmem_ld32(regs, tmem + cc * 32);
            TCG_WAIT_LD();
            const int jj0 = col0 + cc * 32;
            #pragma unroll
            for (int j2 = 0; j2 < 32; ++j2)
                s += tanhf(__uint_as_float(regs[j2]) + hrow[jj0 + j2]) * Va[jj0 + j2];
        }
        float* sm = reinterpret_cast<float*>(smc);
        __syncthreads();
        sm[wid * 32 + lid] = s;
        __syncthreads();
        if (wid < 4)
            C[(size_t)m * NBX_ATT + blockIdx.x] = sm[wid * 32 + lid] + sm[(wid + 4) * 32 + lid];
    } else {
        #pragma unroll
        for (int c = 0; c < 4; ++c) {
            const int cc = hf * 4 + c;
            uint32_t regs[32];
            tmem_ld32(regs, tmem + cc * 32);
            TCG_WAIT_LD();
            const int jj0 = col0 + cc * 32;
            #pragma unroll
            for (int j2 = 0; j2 < 32; j2 += 4) {
                float4 o;
                o.x = __uint_as_float(regs[j2 + 0]);
                o.y = __uint_as_float(regs[j2 + 1]);
                o.z = __uint_as_float(regs[j2 + 2]);
                o.w = __uint_as_float(regs[j2 + 3]);
                if (EMODE == EP_BIAS) {
                    o.x += bias[jj0 + j2 + 0]; o.y += bias[jj0 + j2 + 1];
                    o.z += bias[jj0 + j2 + 2]; o.w += bias[jj0 + j2 + 3];
                }
                *reinterpret_cast<float4*>(&C[(size_t)m * ldc + jj0 + j2]) = o;
            }
        }
    }
    TCG_FENCE_BEFORE();
    __syncthreads();
    if (wid == 0) TCG_DEALLOC(tmem, TN);

#else
    // ============ FFMA fallback (plain-sm_103 pass; dead code on GB300) ============
    float* Bs = reinterpret_cast<float*>(smc);       // 32 x 64 tile of B
    const int Ktot = nK * TK;
    const int mt = tid & 127;
    const int m = row0 + mt;
    float s_att = 0.f;

    for (int nc = 0; nc < 4; ++nc) {
        float acc[64];
        #pragma unroll
        for (int j = 0; j < 64; ++j) acc[j] = 0.f;

        for (int kt = 0; kt < Ktot; kt += 32) {
            for (int i = tid; i < 32 * 64; i += 256) {
                const int kk = i & 31, j = i >> 5;
                Bs[kk * 64 + j] = Bt[(size_t)(col0 + nc * 64 + j) * ldb + kt + kk];
            }
            __syncthreads();
            if (tid < 128) {
                float av[32];
                #pragma unroll
                for (int q = 0; q < 32; q += 4) {
                    float4 v = *reinterpret_cast<const float4*>(&A[(size_t)m * lda + kt + q]);
                    av[q] = v.x; av[q + 1] = v.y; av[q + 2] = v.z; av[q + 3] = v.w;
                }
                #pragma unroll 4
                for (int kk = 0; kk < 32; ++kk) {
                    const float a = av[kk];
                    #pragma unroll
                    for (int j = 0; j < 64; ++j)
                        acc[j] = fmaf(a, Bs[kk * 64 + j], acc[j]);
                }
            }
            __syncthreads();
        }
        if (tid < 128) {
            const int jj0 = col0 + nc * 64;
            if (EMODE == EP_ATT) {
                const int b = m >> 6;
                for (int j = 0; j < 64; ++j)
                    s_att += tanhf(acc[j] + hWa[(size_t)b * UDIM + jj0 + j]) * Va[jj0 + j];
            } else {
                for (int j = 0; j < 64; ++j) {
                    float o = acc[j];
                    if (EMODE == EP_BIAS) o += bias[jj0 + j];
                    C[(size_t)m * ldc + jj0 + j] = o;
                }
            }
        }
    }
    if (EMODE == EP_ATT && tid < 128)
        C[(size_t)m * NBX_ATT + blockIdx.x] = s_att;
#endif
}

// ---------------- softmax over T + context; writes alpha to out, c_t into g_x ----------------
__global__ __launch_bounds__(256)
void attn_kernel(const float* __restrict__ E, float* __restrict__ out)
{
    const int b   = blockIdx.x;
    const int tid = threadIdx.x;
    __shared__ float alpha[TLEN];

    if (tid < TLEN) {
        const float* ep = g_epart + (size_t)(b * TLEN + tid) * NBX_ATT;
        float e = 0.f;
        #pragma unroll
        for (int p = 0; p < NBX_ATT; ++p) e += ep[p];
        alpha[tid] = e;
    }
    __syncthreads();
    if (tid < 32) {
        float v0 = alpha[tid], v1 = alpha[tid + 32];
        float mx = fmaxf(v0, v1);
        #pragma unroll
        for (int off = 16; off > 0; off >>= 1)
            mx = fmaxf(mx, __shfl_xor_sync(0xffffffffu, mx, off));
        float e0 = expf(v0 - mx), e1 = expf(v1 - mx);
        float s = e0 + e1;
        #pragma unroll
        for (int off = 16; off > 0; off >>= 1)
            s += __shfl_xor_sync(0xffffffffu, s, off);
        float inv = 1.f / s;
        alpha[tid]      = e0 * inv;
        alpha[tid + 32] = e1 * inv;
    }
    __syncthreads();
    if (tid < TLEN)
        out[(size_t)b * 1088 + tid] = alpha[tid];

    const float* Eb = E + (size_t)b * TLEN * EDIM;
    float a0 = 0.f, a1 = 0.f, a2 = 0.f, a3 = 0.f;
    for (int t = 0; t < TLEN; ++t) {
        const float w = alpha[t];
        const float* row = Eb + (size_t)t * EDIM;
        a0 = fmaf(w, row[tid +   0], a0);
        a1 = fmaf(w, row[tid + 256], a1);
        a2 = fmaf(w, row[tid + 512], a2);
        a3 = fmaf(w, row[tid + 768], a3);
    }
    float* xr = g_x + (size_t)b * (XDIM + EDIM) + XDIM;   // c_t region, tf32-rounded
    xr[tid +   0] = tf32r(a0);
    xr[tid + 256] = tf32r(a1);
    xr[tid + 512] = tf32r(a2);
    xr[tid + 768] = tf32r(a3);
}

// ---------------- gates: z, r; store z and tf32(r*h) ----------------
__global__ __launch_bounds__(256)
void gates_kernel(const float* __restrict__ h)
{
    const int idx = blockIdx.x * blockDim.x + threadIdx.x;
    if (idx >= BSZ * UDIM) return;
    const int m = idx >> 10;
    const int j = idx & 1023;
    const float* G1 = g_G1 + (size_t)m * 3 * UDIM;
    const float* G2 = g_G2 + (size_t)m * 2 * UDIM;
    float z = fminf(fmaxf(0.2f * (G1[j]        + G2[j])        + 0.5f, 0.f), 1.f);
    float r = fminf(fmaxf(0.2f * (G1[j + 1024] + G2[j + 1024]) + 0.5f, 0.f), 1.f);
    g_z[idx]  = z;
    g_rh[idx] = tf32r(r * h[idx]);   // Python: r*h@rh == (r*h)@rh
}

// ---------------- final: h_new -> out ----------------
__global__ __launch_bounds__(256)
void gru_final_kernel(const float* __restrict__ h, float* __restrict__ out)
{
    const int idx = blockIdx.x * blockDim.x + threadIdx.x;
    if (idx >= BSZ * UDIM) return;
    const int m = idx >> 10;
    const int j = idx & 1023;
    float hh = tanhf(g_G1[(size_t)m * 3 * UDIM + 2048 + j] + g_Ghh[idx]);
    float z  = g_z[idx];
    out[(size_t)m * 1088 + 64 + j] = z * h[idx] + (1.f - z) * hh;
}

// ---------------- launch ----------------
extern "C" void kernel_launch(void* const* d_in, const int* in_sizes, int n_in,
                              void* d_out, int out_size)
{
    (void)in_sizes; (void)n_in; (void)out_size;
    const float* inputs = (const float*)d_in[0];   // (512, 512)
    const float* h      = (const float*)d_in[1];   // (512, 1024)
    const float* E      = (const float*)d_in[2];   // (512, 64, 1024)
    const float* kern   = (const float*)d_in[3];   // (1536, 3072)
    const float* rker   = (const float*)d_in[4];   // (1024, 3072)
    const float* bias   = (const float*)d_in[5];   // (3072,)
    const float* Wa     = (const float*)d_in[6];   // (2048, 1024)
    const float* Va     = (const float*)d_in[7];   // (1024, 1)
    float* out = (float*)d_out;                    // (512, 1088)

    float *tanhE, *tanhH, *h32, *xbuf, *hWa, *epart, *G1, *G2, *rh, *Ghh;
    float *WaTlo, *WaThi, *kernT, *rkerT;
    cudaGetSymbolAddress((void**)&tanhE, g_tanhE);
    cudaGetSymbolAddress((void**)&tanhH, g_tanh_h);
    cudaGetSymbolAddress((void**)&h32,   g_h32);
    cudaGetSymbolAddress((void**)&xbuf,  g_x);
    cudaGetSymbolAddress((void**)&hWa,   g_hWa);
    cudaGetSymbolAddress((void**)&epart, g_epart);
    cudaGetSymbolAddress((void**)&G1,    g_G1);
    cudaGetSymbolAddress((void**)&G2,    g_G2);
    cudaGetSymbolAddress((void**)&rh,    g_rh);
    cudaGetSymbolAddress((void**)&Ghh,   g_Ghh);
    cudaGetSymbolAddress((void**)&WaTlo, g_WaT_lo);
    cudaGetSymbolAddress((void**)&WaThi, g_WaT_hi);
    cudaGetSymbolAddress((void**)&kernT, g_kernT);
    cudaGetSymbolAddress((void**)&rkerT, g_rkerT);

    cudaFuncSetAttribute(tgemm_kernel<EP_STORE>, cudaFuncAttributeMaxDynamicSharedMemorySize, SM_TOTAL);
    cudaFuncSetAttribute(tgemm_kernel<EP_ATT  >, cudaFuncAttributeMaxDynamicSharedMemorySize, SM_TOTAL);
    cudaFuncSetAttribute(tgemm_kernel<EP_BIAS >, cudaFuncAttributeMaxDynamicSharedMemorySize, SM_TOTAL);

    // [0] weight transposes (tf32-rounded)
    transpose_all_kernel<<<9728, dim3(32, 8)>>>(Wa, kern, rker);

    // [1] tanh(E), tf32-rounded
    const int n4 = BSZ * TLEN * EDIM / 4;
    tanh4_kernel<<<n4 / 256, 256>>>((const float4*)E, (float4*)tanhE, n4);

    // [2] prep: tf32(h), tf32(tanh h), g_x[:, :512]
    prep_kernel<<<(BSZ * UDIM + 255) / 256, 256>>>(h, inputs);

    // [3] hWa = tanh(h) @ Wa[:U]            M=512  N=1024 K=1024
    tgemm_kernel<EP_STORE><<<dim3(4, 4), 256, SM_TOTAL>>>(
        tanhH, UDIM, WaTlo, UDIM, 32, hWa, UDIM, nullptr, nullptr, nullptr);

    // [4] attention GEMM + fused e-partials  M=32768 N=1024 K=1024
    tgemm_kernel<EP_ATT><<<dim3(NBX_ATT, 256), 256, SM_TOTAL>>>(
        tanhE, EDIM, WaThi, UDIM, 32, epart, 0, hWa, Va, nullptr);

    // [5] softmax + alpha-out + c_t -> g_x
    attn_kernel<<<BSZ, 256>>>(E, out);

    // [6] G1 = x @ kernel + bias             M=512  N=3072 K=1536
    tgemm_kernel<EP_BIAS><<<dim3(12, 4), 256, SM_TOTAL>>>(
        xbuf, XDIM + EDIM, kernT, XDIM + EDIM, 48, G1, 3 * UDIM, nullptr, nullptr, bias);

    // [7] G2 = h @ rker[:, :2048]            M=512  N=2048 K=1024
    tgemm_kernel<EP_STORE><<<dim3(8, 4), 256, SM_TOTAL>>>(
        h32, UDIM, rkerT, UDIM, 32, G2, 2 * UDIM, nullptr, nullptr, nullptr);

    // [8] gates
    gates_kernel<<<(BSZ * UDIM + 255) / 256, 256>>>(h);

    // [9] Ghh = (r*h) @ rker[:, 2048:]       M=512  N=1024 K=1024
    tgemm_kernel<EP_STORE><<<dim3(4, 4), 256, SM_TOTAL>>>(
        rh, UDIM, rkerT + (size_t)2048 * UDIM, UDIM, 32, Ghh, UDIM, nullptr, nullptr, nullptr);

    // [10] h_new
    gru_final_kernel<<<(BSZ * UDIM + 255) / 256, 256>>>(h, out);
}